// round 16
// baseline (speedup 1.0000x reference)
#include <cuda_runtime.h>
#include <cuda_fp16.h>
#include <math.h>
#include <stdint.h>

// Problem constants
#define NTOK 4096
#define DDIM 512
#define NEXP 8
#define HID  1024
#define NPAIR (NTOK * 2)
#define CC   128
#define HH   32
#define WW   32

typedef __half  f16;
typedef __half2 f162;

// ---------------- static device scratch --------------------------------------
__device__ __align__(256) f16 d_xph[NTOK * DDIM];        // fp16 tokens (GEMM1 A)
__device__ __align__(256) f16 d_heh[NPAIR * HID];        // fp16 swiglu acts (GEMM2 A)
__device__ float d_po [NPAIR * DDIM];                    // gate-scaled outputs
__device__ __align__(256) f16 d_w1h[NEXP * DDIM * 2 * HID];  // w1 fp16
__device__ __align__(256) f16 d_w2h[NEXP * HID * DDIM];      // w2 fp16
__device__ int   d_counts[NEXP];
__device__ int   d_offsets[NEXP];
__device__ int   d_tok_e[NTOK * 2];
__device__ int   d_tok_r[NTOK * 2];
__device__ float d_tok_g[NTOK * 2];
__device__ int   d_tok_pr[NTOK * 2];
__device__ int   d_row_token[NPAIR];
__device__ float d_row_gate[NPAIR];

// ---------------- helpers -----------------------------------------------------
__device__ __forceinline__ uint32_t smem_u32(const void* p) {
    return (uint32_t)__cvta_generic_to_shared(p);
}
__device__ __forceinline__ void ldsm4(uint32_t* r, uint32_t addr) {
    asm volatile("ldmatrix.sync.aligned.m8n8.x4.shared.b16 {%0,%1,%2,%3}, [%4];"
                 : "=r"(r[0]), "=r"(r[1]), "=r"(r[2]), "=r"(r[3]) : "r"(addr));
}
__device__ __forceinline__ void ldsm4t(uint32_t* r, uint32_t addr) {
    asm volatile("ldmatrix.sync.aligned.m8n8.x4.trans.shared.b16 {%0,%1,%2,%3}, [%4];"
                 : "=r"(r[0]), "=r"(r[1]), "=r"(r[2]), "=r"(r[3]) : "r"(addr));
}
__device__ __forceinline__ void mma_f16(float* d, const uint32_t* a, const uint32_t* b) {
    asm volatile(
        "mma.sync.aligned.m16n8k16.row.col.f32.f16.f16.f32 "
        "{%0,%1,%2,%3}, {%4,%5,%6,%7}, {%8,%9}, {%0,%1,%2,%3};"
        : "+f"(d[0]), "+f"(d[1]), "+f"(d[2]), "+f"(d[3])
        : "r"(a[0]), "r"(a[1]), "r"(a[2]), "r"(a[3]), "r"(b[0]), "r"(b[1]));
}
__device__ __forceinline__ void cpa16(uint32_t dst, const void* src) {
    asm volatile("cp.async.cg.shared.global [%0], [%1], 16;" :: "r"(dst), "l"(src));
}
__device__ __forceinline__ void cpa_commit() {
    asm volatile("cp.async.commit_group;" ::: "memory");
}
template<int N> __device__ __forceinline__ void cpa_wait() {
    asm volatile("cp.async.wait_group %0;" :: "n"(N) : "memory");
}

// Tile geometry
#define BM    128
#define BK    64
#define APAD  72     // 64 + 8 halves (144B row stride: conflict-free ldsm)
#define B1PAD 72     // G1 B: 64-wide + 8
#define B2PAD 136    // G2 B: 128-wide + 8
#define A_ELE  (BM * APAD)        // 9216
#define B1_ELE (BK * B1PAD)       // 4608
#define B2_ELE (BK * B2PAD)       // 8704

// ---------------- weight cast + reset (launch 0), vectorized ------------------
__global__ void convert_w_kernel(const float* __restrict__ w1,
                                 const float* __restrict__ w2,
                                 f16* __restrict__ w1h, f16* __restrict__ w2h) {
    const int v1 = (NEXP * DDIM * 2 * HID) / 4;   // float4 count in w1
    const int v2 = (NEXP * HID * DDIM) / 4;
    if (blockIdx.x == 0 && threadIdx.x < NEXP) d_counts[threadIdx.x] = 0;
    int i = blockIdx.x * blockDim.x + threadIdx.x;
    int stride = gridDim.x * blockDim.x;
    for (; i < v1 + v2; i += stride) {
        const float4* src; f16* dst; int j;
        if (i < v1) { src = (const float4*)w1; dst = w1h; j = i; }
        else        { src = (const float4*)w2; dst = w2h; j = i - v1; }
        float4 v = src[j];
        f162 lo = __floats2half2_rn(v.x, v.y);
        f162 hi = __floats2half2_rn(v.z, v.w);
        uint2 pk = make_uint2(*(uint32_t*)&lo, *(uint32_t*)&hi);
        *(uint2*)(dst + j * 4) = pk;
    }
}

// ---------------- patchify + router merged (launch 1) -------------------------
__global__ void __launch_bounds__(256) router_kernel(const float* __restrict__ x,
                                                     const float* __restrict__ rw) {
    __shared__ float rwT[NEXP * DDIM];    // rwT[e*512+k], 16KB
    __shared__ float xs[8][DDIM];         // patchified fp32 tokens, 16KB

    int tid = threadIdx.x;
    int n0  = blockIdx.x * 8;

    for (int i = tid; i < NEXP * DDIM; i += 256) {
        int k = i >> 3, e = i & 7;
        rwT[e * DDIM + k] = rw[i];
    }

#pragma unroll
    for (int i = 0; i < 4; i++) {
        int unit = tid + i * 256;
        int tok = unit & 7;
        int c   = unit >> 3;
        int n = n0 + tok;
        int b  = n >> 8;
        int h2 = (n >> 4) & 15;
        int w2 = n & 15;
        size_t xo = ((size_t)(b * CC + c) * HH + h2 * 2) * WW + w2 * 2;
        float2 v0 = *(const float2*)(x + xo);
        float2 v1 = *(const float2*)(x + xo + WW);
        int d0 = c * 4;
        xs[tok][d0 + 0] = v0.x; xs[tok][d0 + 1] = v0.y;
        xs[tok][d0 + 2] = v1.x; xs[tok][d0 + 3] = v1.y;
        f162 lo = __floats2half2_rn(v0.x, v0.y);
        f162 hi = __floats2half2_rn(v1.x, v1.y);
        *(uint2*)(d_xph + (size_t)n * DDIM + d0) =
            make_uint2(*(uint32_t*)&lo, *(uint32_t*)&hi);
    }
    __syncthreads();

    int warp = tid >> 5, lane = tid & 31;
    int n = n0 + warp;

    float acc[NEXP];
#pragma unroll
    for (int e = 0; e < NEXP; e++) acc[e] = 0.f;
#pragma unroll
    for (int t = 0; t < 4; t++) {
        int k4 = (lane + t * 32) * 4;
        float4 xv = *(const float4*)&xs[warp][k4];
#pragma unroll
        for (int e = 0; e < NEXP; e++) {
            const float4 wv = *(const float4*)&rwT[e * DDIM + k4];
            acc[e] += xv.x * wv.x + xv.y * wv.y + xv.z * wv.z + xv.w * wv.w;
        }
    }
#pragma unroll
    for (int e = 0; e < NEXP; e++) {
#pragma unroll
        for (int off = 16; off > 0; off >>= 1)
            acc[e] += __shfl_xor_sync(0xFFFFFFFFu, acc[e], off);
    }
    if (lane == 0) {
        int i0 = 0; float l0 = acc[0];
#pragma unroll
        for (int e = 1; e < NEXP; e++) if (acc[e] > l0) { l0 = acc[e]; i0 = e; }
        int i1 = -1; float l1 = -1e30f;
#pragma unroll
        for (int e = 0; e < NEXP; e++) if (e != i0 && acc[e] > l1) { l1 = acc[e]; i1 = e; }
        float g0 = 1.f / (1.f + expf(l1 - l0));
        float g1 = 1.f - g0;
        int r0 = atomicAdd(&d_counts[i0], 1);
        int r1 = atomicAdd(&d_counts[i1], 1);
        d_tok_e[n * 2 + 0] = i0; d_tok_r[n * 2 + 0] = r0; d_tok_g[n * 2 + 0] = g0;
        d_tok_e[n * 2 + 1] = i1; d_tok_r[n * 2 + 1] = r1; d_tok_g[n * 2 + 1] = g1;
    }
}

// ---------------- scatter + offsets (launch 2): per-block local prefix --------
__global__ void scatter_kernel() {
    __shared__ int off_s[NEXP];
    int tid = threadIdx.x;
    if (tid == 0) {
        int s = 0;
#pragma unroll
        for (int e = 0; e < NEXP; e++) {
            off_s[e] = s;
            if (blockIdx.x == 0) d_offsets[e] = s;
            s += d_counts[e];
        }
    }
    __syncthreads();
    int n = blockIdx.x * blockDim.x + tid;
    if (n >= NTOK) return;
#pragma unroll
    for (int j = 0; j < 2; j++) {
        int e = d_tok_e[n * 2 + j];
        int pr = off_s[e] + d_tok_r[n * 2 + j];
        d_row_token[pr] = n;
        d_row_gate[pr]  = d_tok_g[n * 2 + j];
        d_tok_pr[n * 2 + j] = pr;
    }
}

// ---------------- GEMM1 (launch 3, ncu window): fused SwiGLU ------------------
#define G1_STG (A_ELE + 2 * B1_ELE)        // 18432 elems / stage
#define G1_SMEM (2 * G1_STG * 2)           // 73728 B
__global__ void __launch_bounds__(256, 3) gemm1_kernel() {
    extern __shared__ f16 S[];
    __shared__ int rows_s[BM];

    int e    = blockIdx.z;
    int cnt  = d_counts[e];
    int row0 = blockIdx.y * BM;
    if (row0 >= cnt) return;
    int base = d_offsets[e];
    int jn0  = blockIdx.x * 64;

    int tid  = threadIdx.x;
    int lane = tid & 31;
    int wid  = tid >> 5;
    int wm   = wid >> 1;          // 0..3
    int wn   = wid & 1;           // 0..1
    int lm   = lane & 15;
    int lq   = lane >> 4;

    if (tid < BM) {
        int rr = row0 + tid;
        rows_s[tid] = d_row_token[base + ((rr < cnt) ? rr : (cnt - 1))];
    }
    __syncthreads();

    const f16* w1h = d_w1h + (size_t)e * DDIM * 2 * HID;

    // precomputed smem byte addresses (stage 0 / stage 1)
    uint32_t sbase = smem_u32(S);
    uint32_t a_rd0 = sbase + ((wm * 32 + lm) * APAD + lq * 8) * 2;
    uint32_t b_rd0 = sbase + (A_ELE + lm * B1PAD + wn * 32 + lq * 8) * 2;

    float accV[2][4][4], accG[2][4][4];
#pragma unroll
    for (int a = 0; a < 2; a++)
#pragma unroll
        for (int b = 0; b < 4; b++)
#pragma unroll
            for (int c = 0; c < 4; c++) { accV[a][b][c] = 0.f; accG[a][b][c] = 0.f; }

#define G1_LOAD(st, k0)                                                          \
    {                                                                            \
        f16* Ah = S + (st) * G1_STG;                                             \
        f16* Bvh = Ah + A_ELE;                                                   \
        f16* Bgh = Bvh + B1_ELE;                                                 \
        _Pragma("unroll")                                                        \
        for (int i = 0; i < 4; i++) {                                            \
            int id = tid + i * 256;                                              \
            int r = id >> 3, c = (id & 7) * 8;                                   \
            size_t go = (size_t)rows_s[r] * DDIM + (k0) + c;                     \
            cpa16(smem_u32(Ah + r * APAD + c), d_xph + go);                      \
        }                                                                        \
        _Pragma("unroll")                                                        \
        for (int i = 0; i < 2; i++) {                                            \
            int id = tid + i * 256;                                              \
            int kk = id >> 3, c = (id & 7) * 8;                                  \
            size_t gv = (size_t)((k0) + kk) * (2 * HID) + jn0 + c;               \
            cpa16(smem_u32(Bvh + kk * B1PAD + c), w1h + gv);                     \
            cpa16(smem_u32(Bgh + kk * B1PAD + c), w1h + gv + HID);               \
        }                                                                        \
    }

    G1_LOAD(0, 0);
    cpa_commit();

    for (int ch = 0; ch < DDIM / BK; ch++) {
        if (ch + 1 < DDIM / BK) {
            G1_LOAD((ch + 1) & 1, (ch + 1) * BK);
            cpa_commit();
            cpa_wait<1>();
        } else {
            cpa_wait<0>();
        }
        __syncthreads();

        uint32_t stoff = (ch & 1) * (G1_STG * 2);
        uint32_t ard = a_rd0 + stoff;
        uint32_t brd = b_rd0 + stoff;

#pragma unroll
        for (int s = 0; s < 4; s++) {
            uint32_t ah[2][4];
#pragma unroll
            for (int tm = 0; tm < 2; tm++)
                ldsm4(ah[tm], ard + (tm * 16 * APAD + s * 16) * 2);
            uint32_t bvh[2][4], bgh[2][4];
#pragma unroll
            for (int nt = 0; nt < 2; nt++) {
                uint32_t bo = brd + (s * 16 * B1PAD + nt * 16) * 2;
                ldsm4t(bvh[nt], bo);
                ldsm4t(bgh[nt], bo + B1_ELE * 2);
            }
#pragma unroll
            for (int tm = 0; tm < 2; tm++) {
#pragma unroll
                for (int j = 0; j < 4; j++) {
                    int nt = j >> 1, o = (j & 1) * 2;
                    mma_f16(accV[tm][j], ah[tm], &bvh[nt][o]);
                    mma_f16(accG[tm][j], ah[tm], &bgh[nt][o]);
                }
            }
        }
        __syncthreads();
    }

    // epilogue: SwiGLU -> fp16 he
    int qr = lane >> 2, qc = lane & 3;
#pragma unroll
    for (int tm = 0; tm < 2; tm++) {
#pragma unroll
        for (int p = 0; p < 2; p++) {
            int rl = wm * 32 + tm * 16 + qr + p * 8;
            int r  = row0 + rl;
            if (r >= cnt) continue;
            size_t ho = (size_t)(base + r) * HID;
#pragma unroll
            for (int j = 0; j < 4; j++) {
                float v0 = accV[tm][j][p * 2], v1 = accV[tm][j][p * 2 + 1];
                float g0 = accG[tm][j][p * 2], g1 = accG[tm][j][p * 2 + 1];
                float o0 = v0 / (1.f + expf(-g0));
                float o1 = v1 / (1.f + expf(-g1));
                int col = jn0 + wn * 32 + j * 8 + qc * 2;
                *(f162*)&d_heh[ho + col] = __floats2half2_rn(o0, o1);
            }
        }
    }
}

// ---------------- GEMM2 (launch 4): 128x128, BK=64, gated --------------------
#define G2_STG (A_ELE + B2_ELE)            // 17920 elems / stage
#define G2_SMEM (2 * G2_STG * 2)           // 71680 B
__global__ void __launch_bounds__(256, 3) gemm2_kernel() {
    extern __shared__ f16 S[];
    __shared__ float gate_s[BM];

    int e    = blockIdx.z;
    int cnt  = d_counts[e];
    int row0 = blockIdx.y * BM;
    if (row0 >= cnt) return;
    int base = d_offsets[e];
    int n0   = blockIdx.x * 128;

    int tid  = threadIdx.x;
    int lane = tid & 31;
    int wid  = tid >> 5;
    int wm   = wid >> 1;          // 0..3 (32 rows each)
    int wn   = wid & 1;           // 0..1 (64 cols each)
    int lm   = lane & 15;
    int lq   = lane >> 4;

    if (tid < BM) {
        int rr = row0 + tid;
        gate_s[tid] = (rr < cnt) ? d_row_gate[base + rr] : 0.f;
    }
    __syncthreads();

    const f16* w2h = d_w2h + (size_t)e * HID * DDIM;

    uint32_t sbase = smem_u32(S);
    uint32_t a_rd0 = sbase + ((wm * 32 + lm) * APAD + lq * 8) * 2;
    uint32_t b_rd0 = sbase + (A_ELE + lm * B2PAD + wn * 64 + lq * 8) * 2;

    float acc[2][8][4];
#pragma unroll
    for (int a = 0; a < 2; a++)
#pragma unroll
        for (int b = 0; b < 8; b++)
#pragma unroll
            for (int c = 0; c < 4; c++) acc[a][b][c] = 0.f;

#define G2_LOAD(st, k0)                                                          \
    {                                                                            \
        f16* Ah = S + (st) * G2_STG;                                             \
        f16* Bh = Ah + A_ELE;                                                    \
        _Pragma("unroll")                                                        \
        for (int i = 0; i < 4; i++) {                                            \
            int id = tid + i * 256;                                              \
            int r = id >> 3, c = (id & 7) * 8;                                   \
            int rr = row0 + r; if (rr >= cnt) rr = cnt - 1;                      \
            size_t go = (size_t)(base + rr) * HID + (k0) + c;                    \
            cpa16(smem_u32(Ah + r * APAD + c), d_heh + go);                      \
        }                                                                        \
        _Pragma("unroll")                                                        \
        for (int i = 0; i < 4; i++) {                                            \
            int id = tid + i * 256;                                              \
            int kk = id >> 4, c = (id & 15) * 8;                                 \
            size_t gb = (size_t)((k0) + kk) * DDIM + n0 + c;                     \
            cpa16(smem_u32(Bh + kk * B2PAD + c), w2h + gb);                      \
        }                                                                        \
    }

    G2_LOAD(0, 0);
    cpa_commit();

    for (int ch = 0; ch < HID / BK; ch++) {
        if (ch + 1 < HID / BK) {
            G2_LOAD((ch + 1) & 1, (ch + 1) * BK);
            cpa_commit();
            cpa_wait<1>();
        } else {
            cpa_wait<0>();
        }
        __syncthreads();

        uint32_t stoff = (ch & 1) * (G2_STG * 2);
        uint32_t ard = a_rd0 + stoff;
        uint32_t brd = b_rd0 + stoff;

#pragma unroll
        for (int s = 0; s < 4; s++) {
            uint32_t ah[2][4];
#pragma unroll
            for (int tm = 0; tm < 2; tm++)
                ldsm4(ah[tm], ard + (tm * 16 * APAD + s * 16) * 2);
            uint32_t bh[4][4];
#pragma unroll
            for (int nt = 0; nt < 4; nt++)
                ldsm4t(bh[nt], brd + (s * 16 * B2PAD + nt * 16) * 2);
#pragma unroll
            for (int tm = 0; tm < 2; tm++) {
#pragma unroll
                for (int j = 0; j < 8; j++) {
                    int nt = j >> 1, o = (j & 1) * 2;
                    mma_f16(acc[tm][j], ah[tm], &bh[nt][o]);
                }
            }
        }
        __syncthreads();
    }

    int qr = lane >> 2, qc = lane & 3;
#pragma unroll
    for (int tm = 0; tm < 2; tm++) {
#pragma unroll
        for (int p = 0; p < 2; p++) {
            int rl = wm * 32 + tm * 16 + qr + p * 8;
            int r  = row0 + rl;
            if (r >= cnt) continue;
            float g = gate_s[rl];
            size_t po = (size_t)(base + r) * DDIM;
#pragma unroll
            for (int j = 0; j < 8; j++) {
                int col = n0 + wn * 64 + j * 8 + qc * 2;
                float2 o = make_float2(g * acc[tm][j][p * 2], g * acc[tm][j][p * 2 + 1]);
                *(float2*)&d_po[po + col] = o;
            }
        }
    }
}

// ---------------- combine (launch 5): float2 per thread -----------------------
__global__ void combine_kernel(float* __restrict__ y) {
    int idx = blockIdx.x * blockDim.x + threadIdx.x;    // NTOK*DDIM/2 threads
    if (idx >= NTOK * DDIM / 2) return;
    int w2 = idx & 15;
    int h  = (idx >> 4) & 31;
    int c  = (idx >> 9) & 127;
    int b  = idx >> 16;
    int n  = (b << 8) + ((h >> 1) << 4) + w2;
    int d0 = (c << 2) + ((h & 1) << 1);
    int pr0 = d_tok_pr[n * 2 + 0];
    int pr1 = d_tok_pr[n * 2 + 1];
    float2 a = *(const float2*)&d_po[(size_t)pr0 * DDIM + d0];
    float2 bb = *(const float2*)&d_po[(size_t)pr1 * DDIM + d0];
    size_t yo = ((size_t)(b * CC + c) * HH + h) * WW + w2 * 2;
    *(float2*)(y + yo) = make_float2(a.x + bb.x, a.y + bb.y);
}

// ---------------- launch -----------------------------------------------------
extern "C" void kernel_launch(void* const* d_in, const int* in_sizes, int n_in,
                              void* d_out, int out_size) {
    const float* x  = (const float*)d_in[0];
    const float* rw = (const float*)d_in[1];
    const float* w1 = (const float*)d_in[2];
    const float* w2 = (const float*)d_in[3];
    float* y = (float*)d_out;

    cudaFuncSetAttribute(gemm1_kernel, cudaFuncAttributeMaxDynamicSharedMemorySize, G1_SMEM);
    cudaFuncSetAttribute(gemm2_kernel, cudaFuncAttributeMaxDynamicSharedMemorySize, G2_SMEM);

    f16 *w1h, *w2h;
    cudaGetSymbolAddress((void**)&w1h, d_w1h);
    cudaGetSymbolAddress((void**)&w2h, d_w2h);

    convert_w_kernel<<<1024, 256>>>(w1, w2, w1h, w2h);                        // 0 (+reset)
    router_kernel<<<NTOK / 8, 256>>>(x, rw);                                  // 1 (patchify+router)
    scatter_kernel<<<(NTOK + 255) / 256, 256>>>();                            // 2 (+offsets)
    gemm1_kernel<<<dim3(HID / 64, NTOK / BM, NEXP), 256, G1_SMEM>>>();        // 3 (ncu window)
    gemm2_kernel<<<dim3(DDIM / 128, NTOK / BM, NEXP), 256, G2_SMEM>>>();      // 4
    combine_kernel<<<(NTOK * DDIM / 2 + 255) / 256, 256>>>(y);                // 5
}